// round 2
// baseline (speedup 1.0000x reference)
#include <cuda_runtime.h>
#include <cstdint>

#define BATCH 4
#define NPTS  8192
#define RT    128          // rows (pred points) per block
#define CG    1024         // cols (gt points) per block (col-group)
#define CT    128          // cols per inner tile
#define NRT   (NPTS/RT)    // 64 row tiles
#define NCG   (NPTS/CG)    // 8  col groups

// Scratch (disjoint writers per launch -> no init, no atomics, deterministic)
__device__ float g_rpart[NCG * BATCH * NPTS];   // [cg][b][n] : min over cg's 1024 gt cols
__device__ float g_cpart[NRT * BATCH * NPTS];   // [rt][b][m] : min over rt's 128 pred rows
__device__ float g_pr[128], g_pc[128];          // block partial sums

// ---- packed f32x2 helpers (sm_100+) ----
__device__ __forceinline__ unsigned long long pk2(float lo, float hi) {
    unsigned long long r;
    asm("mov.b64 %0, {%1, %2};" : "=l"(r) : "f"(lo), "f"(hi));
    return r;
}
__device__ __forceinline__ void upk2(unsigned long long v, float& lo, float& hi) {
    asm("mov.b64 {%0, %1}, %2;" : "=f"(lo), "=f"(hi) : "l"(v));
}
__device__ __forceinline__ unsigned long long ffma2(unsigned long long a,
                                                    unsigned long long b,
                                                    unsigned long long c) {
    unsigned long long d;
    asm("fma.rn.f32x2 %0, %1, %2, %3;" : "=l"(d) : "l"(a), "l"(b), "l"(c));
    return d;
}
__device__ __forceinline__ unsigned long long fadd2(unsigned long long a,
                                                    unsigned long long b) {
    unsigned long long d;
    asm("add.rn.f32x2 %0, %1, %2;" : "=l"(d) : "l"(a), "l"(b));
    return d;
}

// ============================================================================
// Main fused kernel: block = (col-group cg, row-tile rt, batch b)
// 256 threads as 16x16 (tx: 8 cols each, ty: 8 rows each).
// dist(n,m) = ||p||^2 + ||g||^2 - 2 p.g, computed as
//   s = fma(-2py, gy, fma(-2px, gx, g2))   (g2 = gx^2+gy^2)
//   row-min accumulates s (add ||p||^2 once at the end)
//   col-min uses d = s + ||p||^2
// ============================================================================
__global__ __launch_bounds__(256) void chamfer_tile(const float* __restrict__ pred,
                                                    const float* __restrict__ gt) {
    const int cg = blockIdx.x, rt = blockIdx.y, b = blockIdx.z;
    const int tid = threadIdx.x;
    const int tx = tid & 15, ty = tid >> 4;

    __shared__ float s_praw[RT * 2];                                 // raw pred (x,y interleaved)
    __shared__ __align__(16) float s_px2[RT], s_py2[RT], s_x2[RT];   // -2px, -2py, px^2+py^2
    __shared__ __align__(16) float s_gx[CG], s_gy[CG], s_g2[CG];     // gx, gy, gx^2+gy^2
    __shared__ float s_red[16][CT + 4];                              // reduce buffer

    // Raw coalesced loads
    s_praw[tid] = pred[((size_t)b * NPTS + (size_t)rt * RT) * 2 + tid];
    #pragma unroll
    for (int k = 0; k < 8; k++) {
        int idx = tid + k * 256;
        float v = gt[((size_t)b * NPTS + (size_t)cg * CG) * 2 + idx];
        int i = idx >> 1;
        if (idx & 1) s_gy[i] = v; else s_gx[i] = v;
    }
    __syncthreads();

    // Derived per-point quantities (now both components are visible)
    if (tid < RT) {
        float px = s_praw[2 * tid], py = s_praw[2 * tid + 1];
        s_px2[tid] = -2.0f * px;
        s_py2[tid] = -2.0f * py;
        s_x2[tid]  = px * px + py * py;
    }
    #pragma unroll
    for (int k = 0; k < 4; k++) {
        int i = tid + k * 256;
        float gx = s_gx[i], gy = s_gy[i];
        s_g2[i] = gx * gx + gy * gy;
    }
    __syncthreads();

    // Per-thread row operands, packed into f32x2 broadcasts
    const int r0 = ty * 8;
    unsigned long long px2p[8], py2p[8], x2p[8];
    float x2s[8], racc[8];
    #pragma unroll
    for (int r = 0; r < 8; r++) {
        float a = s_px2[r0 + r]; px2p[r] = pk2(a, a);
        float c = s_py2[r0 + r]; py2p[r] = pk2(c, c);
        float e = s_x2[r0 + r];  x2s[r] = e; x2p[r] = pk2(e, e);
        racc[r] = 3.4e38f;
    }

    const int cb0 = tx * 8;
    #pragma unroll 1
    for (int ct = 0; ct < CG / CT; ct++) {
        float cacc[8];
        #pragma unroll
        for (int i = 0; i < 8; i++) cacc[i] = 3.4e38f;
        const int cb = ct * CT + cb0;

        #pragma unroll
        for (int cp = 0; cp < 4; cp++) {
            unsigned long long gxp = *(const unsigned long long*)&s_gx[cb + 2 * cp];
            unsigned long long gyp = *(const unsigned long long*)&s_gy[cb + 2 * cp];
            unsigned long long g2p = *(const unsigned long long*)&s_g2[cb + 2 * cp];
            #pragma unroll
            for (int r = 0; r < 8; r++) {
                unsigned long long s = ffma2(px2p[r], gxp, g2p);   // -2px*gx + g2
                s = ffma2(py2p[r], gyp, s);                        // += -2py*gy
                float lo, hi; upk2(s, lo, hi);
                racc[r] = fminf(racc[r], fminf(lo, hi));           // row-min (excl x2)
                unsigned long long d = fadd2(s, x2p[r]);           // full distance
                float dlo, dhi; upk2(d, dlo, dhi);
                cacc[2 * cp]     = fminf(cacc[2 * cp],     dlo);
                cacc[2 * cp + 1] = fminf(cacc[2 * cp + 1], dhi);
            }
        }

        // Flush column mins for this 128-col tile: reduce over 16 ty groups
        __syncthreads();                       // protect s_red reuse
        #pragma unroll
        for (int i = 0; i < 8; i++) s_red[ty][cb0 + i] = cacc[i];
        __syncthreads();
        if (tid < CT) {
            float m = s_red[0][tid];
            #pragma unroll
            for (int k = 1; k < 16; k++) m = fminf(m, s_red[k][tid]);
            g_cpart[((size_t)rt * BATCH + b) * NPTS + (size_t)cg * CG + ct * CT + tid] = m;
        }
    }

    // Flush row mins: reduce over 16 tx groups
    __syncthreads();
    #pragma unroll
    for (int r = 0; r < 8; r++) s_red[tx][r0 + r] = x2s[r] + racc[r];
    __syncthreads();
    if (tid < RT) {
        float m = s_red[0][tid];
        #pragma unroll
        for (int k = 1; k < 16; k++) m = fminf(m, s_red[k][tid]);
        g_rpart[((size_t)cg * BATCH + b) * NPTS + (size_t)rt * RT + tid] = m;
    }
}

// ============================================================================
// Reduce 1: 32768 threads; thread g finishes row-entry g (min over 8 col-group
// partials) and col-entry g (min over 64 row-tile partials); block-sums both.
// ============================================================================
__global__ __launch_bounds__(256) void chamfer_reduce1() {
    const int t = threadIdx.x;
    const int g = blockIdx.x * 256 + t;   // 0..32767

    float rm = g_rpart[g];
    #pragma unroll
    for (int k = 1; k < NCG; k++) rm = fminf(rm, g_rpart[(size_t)k * BATCH * NPTS + g]);
    float cm = g_cpart[g];
    #pragma unroll
    for (int k = 1; k < NRT; k++) cm = fminf(cm, g_cpart[(size_t)k * BATCH * NPTS + g]);

    __shared__ float sr[256], sc[256];
    sr[t] = rm; sc[t] = cm;
    __syncthreads();
    for (int off = 128; off > 0; off >>= 1) {
        if (t < off) { sr[t] += sr[t + off]; sc[t] += sc[t + off]; }
        __syncthreads();
    }
    if (t == 0) { g_pr[blockIdx.x] = sr[0]; g_pc[blockIdx.x] = sc[0]; }
}

// ============================================================================
// Reduce 2: single block sums the 128 partials (fixed order -> deterministic)
// chamfer = mean(row mins) + mean(col mins), each over B*NPTS values.
// ============================================================================
__global__ void chamfer_reduce2(float* __restrict__ out) {
    __shared__ float sr[128], sc[128];
    const int t = threadIdx.x;   // 128 threads
    sr[t] = g_pr[t]; sc[t] = g_pc[t];
    __syncthreads();
    for (int off = 64; off > 0; off >>= 1) {
        if (t < off) { sr[t] += sr[t + off]; sc[t] += sc[t + off]; }
        __syncthreads();
    }
    if (t == 0) out[0] = (sr[0] + sc[0]) * (1.0f / (float)(BATCH * NPTS));
}

extern "C" void kernel_launch(void* const* d_in, const int* in_sizes, int n_in,
                              void* d_out, int out_size) {
    const float* pred = (const float*)d_in[0];
    const float* gt   = (const float*)d_in[1];

    dim3 grid(NCG, NRT, BATCH);          // 8 x 64 x 4 = 2048 blocks
    chamfer_tile<<<grid, 256>>>(pred, gt);
    chamfer_reduce1<<<128, 256>>>();
    chamfer_reduce2<<<1, 128>>>((float*)d_out);
}